// round 7
// baseline (speedup 1.0000x reference)
#include <cuda_runtime.h>
#include <math.h>
#include <stdint.h>

// Problem constants
#define BSZ  128
#define TLEN 512
// H1=256, H2=128, H3=64

// ---------------------------------------------------------------------------
// Static device scratch (no runtime allocation).
// g_xg  : input-gate projections for current layer, [B*T, 3H], max 3H=768
// g_seq : sequence output of current layer,         [B*T, H],  max H=256
// g_hA  : final hidden state of layer 3, [B, 64]
// Every region is fully rewritten before being read on each call.
// ---------------------------------------------------------------------------
__device__ float g_xg[(size_t)BSZ * TLEN * 768];
__device__ float g_seq[(size_t)BSZ * TLEN * 256];
__device__ float g_hA[BSZ * 64];

__device__ __forceinline__ float sigf(float x) { return 1.0f / (1.0f + expf(-x)); }

__device__ __forceinline__ uint32_t smem_u32(const void* p) {
    uint32_t a;
    asm("{ .reg .u64 t; cvta.to.shared.u64 t, %1; cvt.u32.u64 %0, t; }"
        : "=r"(a) : "l"(p));
    return a;
}

__device__ __forceinline__ void st_cluster_f32(uint32_t laddr, uint32_t rank, float v) {
    uint32_t r;
    asm volatile("mapa.shared::cluster.u32 %0, %1, %2;" : "=r"(r) : "r"(laddr), "r"(rank));
    asm volatile("st.shared::cluster.b32 [%0], %1;" :: "r"(r), "r"(__float_as_uint(v)) : "memory");
}

#define CLUSTER_SYNC_ASM() do {                                          \
    asm volatile("barrier.cluster.arrive.aligned;" ::: "memory");        \
    asm volatile("barrier.cluster.wait.aligned;"   ::: "memory");        \
} while (0)

// ---------------------------------------------------------------------------
// Tiled SGEMM with bias:  g_xg[m, n] = X[m, :] . W[:, n] + bias[n]
//   X: [M, K] row-major (Xin, or g_seq when Xin == nullptr)
//   W: [K, N] row-major
// 64x64 tile per CTA, BK=16, 256 threads, 4x4 micro-tile.
// Requires M%64==0, N%64==0, K%16==0 (holds for all layers).
// ---------------------------------------------------------------------------
__global__ void gemm_bias_kernel(const float* __restrict__ Xin,
                                 const float* __restrict__ W,
                                 const float* __restrict__ bias,
                                 int K, int N)
{
    const float* __restrict__ X = Xin ? Xin : g_seq;

    __shared__ float As[16][64];
    __shared__ float Bs[16][64];

    const int m0 = blockIdx.y * 64;
    const int n0 = blockIdx.x * 64;
    const int tx = threadIdx.x;
    const int ty = threadIdx.y;
    const int tid = ty * 16 + tx;

    const int arow = tid >> 2;
    const int acol = (tid & 3) * 4;
    const int brow = tid >> 4;
    const int bcol = (tid & 15) * 4;

    float acc[4][4];
#pragma unroll
    for (int i = 0; i < 4; i++)
#pragma unroll
        for (int j = 0; j < 4; j++) acc[i][j] = 0.0f;

    for (int k0 = 0; k0 < K; k0 += 16) {
        float4 av = *(const float4*)&X[(size_t)(m0 + arow) * K + k0 + acol];
        As[acol + 0][arow] = av.x;
        As[acol + 1][arow] = av.y;
        As[acol + 2][arow] = av.z;
        As[acol + 3][arow] = av.w;

        float4 bv = *(const float4*)&W[(size_t)(k0 + brow) * N + n0 + bcol];
        *(float4*)&Bs[brow][bcol] = bv;

        __syncthreads();

#pragma unroll
        for (int kk = 0; kk < 16; kk++) {
            float a[4], b[4];
#pragma unroll
            for (int i = 0; i < 4; i++) a[i] = As[kk][ty * 4 + i];
#pragma unroll
            for (int j = 0; j < 4; j++) b[j] = Bs[kk][tx * 4 + j];
#pragma unroll
            for (int i = 0; i < 4; i++)
#pragma unroll
                for (int j = 0; j < 4; j++) acc[i][j] += a[i] * b[j];
        }
        __syncthreads();
    }

    float bb[4];
#pragma unroll
    for (int j = 0; j < 4; j++) bb[j] = bias[n0 + tx * 4 + j];

#pragma unroll
    for (int i = 0; i < 4; i++) {
        int m = m0 + ty * 4 + i;
        float4 o;
        o.x = acc[i][0] + bb[0];
        o.y = acc[i][1] + bb[1];
        o.z = acc[i][2] + bb[2];
        o.w = acc[i][3] + bb[3];
        *(float4*)&g_xg[(size_t)m * N + n0 + tx * 4] = o;
    }
}

// ---------------------------------------------------------------------------
// Persistent GRU layer, U fits in one CTA's smem (layers 2 and 3).
// One CTA per batch row: grid = 128, block = 3H threads.
// Thread c owns gate-column c for all 512 steps.
//   pres[c] = h . U[:,c] + brec[c];  then threads i<H combine gates.
// ---------------------------------------------------------------------------
template <int H, bool RELU, bool WSEQ>
__global__ void __launch_bounds__(3 * H, 1)
gru_layer_smem_kernel(const float* __restrict__ U,
                      const float* __restrict__ brec)
{
    constexpr int NC = 3 * H;
    constexpr int Hp = H + 4;          // pad: Hp % 32 == 4 -> conflict-free LDS.128

    extern __shared__ float smem[];
    float* UsT  = smem;                 // [NC][Hp], transposed U
    float* hs   = UsT + NC * Hp;        // [H]
    float* pres = hs + H;               // [NC]
    float* xsm  = pres + NC;            // [NC]

    const int b = blockIdx.x;
    const int c = threadIdx.x;          // gate column

    // Load U transposed into smem (coalesced global reads).
    for (int idx = c; idx < H * NC; idx += NC) {
        int k = idx / NC, cc = idx % NC;
        UsT[cc * Hp + k] = U[idx];
    }
    if (c < H) hs[c] = 0.0f;
    const float br = brec[c];
    __syncthreads();

    const float4* u4 = (const float4*)(UsT + c * Hp);
    const float4* h4 = (const float4*)hs;
    const float* xgb = &g_xg[(size_t)b * TLEN * NC + c];

    float xv = xgb[0];                  // prefetch t=0
    for (int t = 0; t < TLEN; t++) {
        // prefetch next step's xg while computing this step
        float xn = xgb[(size_t)(t + 1 < TLEN ? t + 1 : t) * NC];

        float4 a4 = make_float4(0.f, 0.f, 0.f, 0.f);
#pragma unroll 8
        for (int kq = 0; kq < H / 4; kq++) {
            float4 u = u4[kq];
            float4 hv = h4[kq];          // broadcast across lanes
            a4.x += u.x * hv.x;
            a4.y += u.y * hv.y;
            a4.z += u.z * hv.z;
            a4.w += u.w * hv.w;
        }
        pres[c] = (a4.x + a4.y) + (a4.z + a4.w) + br;
        xsm[c]  = xv;
        __syncthreads();

        if (c < H) {
            float z = sigf(xsm[c] + pres[c]);
            float r = sigf(xsm[H + c] + pres[H + c]);
            float cand = xsm[2 * H + c] + r * pres[2 * H + c];
            float hh = RELU ? fmaxf(cand, 0.0f) : sigf(cand);
            float hn = z * hs[c] + (1.0f - z) * hh;
            hs[c] = hn;
            if (WSEQ)
                g_seq[((size_t)b * TLEN + t) * H + c] = hn;
            else if (t == TLEN - 1)
                g_hA[b * H + c] = hn;
        }
        __syncthreads();
        xv = xn;
    }
}

// ---------------------------------------------------------------------------
// Persistent GRU layer 1 (H=256): U1 = 768 KB split across a 4-CTA cluster.
// Cluster rank r owns i in [r*64, (r+1)*64) -> 192 gate-columns in smem.
// Each cluster processes 4 batch rows; grid = (4, 32) -> 32 clusters.
// Per step: local dot products, per-CTA gate combine, DSMEM broadcast of the
// new h slice to all 4 CTAs, barrier.cluster.
// ---------------------------------------------------------------------------
__global__ void __cluster_dims__(4, 1, 1) __launch_bounds__(192, 1)
gru_layer1_kernel(const float* __restrict__ U,
                  const float* __restrict__ brec)
{
    constexpr int H = 256, NC3 = 768;
    constexpr int LC = 192;            // local gate-columns per CTA
    constexpr int Hp = 260;            // pad: 260 % 32 == 4
    constexpr int NB = 4;              // batches per cluster

    extern __shared__ float smem[];
    float* UsT  = smem;                       // [192][260]
    float* hsb  = UsT + LC * Hp;              // [2][NB][256] double-buffered h
    float* pres = hsb + 2 * NB * H;           // [NB][192]
    float* xsm  = pres + NB * LC;             // [NB][192]

    const int lc = threadIdx.x;               // 0..191
    uint32_t rank;
    asm("mov.u32 %0, %%cluster_ctarank;" : "=r"(rank));
    const int bgrp = blockIdx.y;              // 0..31

    // Load this CTA's U slice, transposed.
    for (int idx = lc; idx < H * LC; idx += LC) {
        int k = idx / LC, cc = idx % LC;
        int gg = cc >> 6, il = cc & 63;
        UsT[cc * Hp + k] = U[(size_t)k * NC3 + gg * H + rank * 64 + il];
    }
    for (int idx = lc; idx < 2 * NB * H; idx += LC) hsb[idx] = 0.0f;

    const int gg = lc >> 6, il = lc & 63;
    const int gc = gg * H + rank * 64 + il;   // global gate column
    const float br = brec[gc];
    const uint32_t hsb_u32 = smem_u32(hsb);

    __syncthreads();
    CLUSTER_SYNC_ASM();                       // all CTAs initialized

    const float4* u4 = (const float4*)(UsT + lc * Hp);

    // prefetch xg for t=0
    float xv[NB];
#pragma unroll
    for (int bs = 0; bs < NB; bs++)
        xv[bs] = g_xg[((size_t)(bgrp * NB + bs) * TLEN + 0) * NC3 + gc];

    for (int t = 0; t < TLEN; t++) {
        const int cur = t & 1;
        const float* hc = hsb + cur * (NB * H);
        const int tn = (t + 1 < TLEN) ? t + 1 : t;

        float xn[NB];
#pragma unroll
        for (int bs = 0; bs < NB; bs++)
            xn[bs] = g_xg[((size_t)(bgrp * NB + bs) * TLEN + tn) * NC3 + gc];

        float4 acc[NB];
#pragma unroll
        for (int bs = 0; bs < NB; bs++) acc[bs] = make_float4(0.f, 0.f, 0.f, 0.f);

        const float4* h40 = (const float4*)(hc + 0 * H);
        const float4* h41 = (const float4*)(hc + 1 * H);
        const float4* h42 = (const float4*)(hc + 2 * H);
        const float4* h43 = (const float4*)(hc + 3 * H);

#pragma unroll 4
        for (int kq = 0; kq < H / 4; kq++) {
            float4 u = u4[kq];
            float4 v0 = h40[kq], v1 = h41[kq], v2 = h42[kq], v3 = h43[kq];
            acc[0].x += u.x * v0.x; acc[0].y += u.y * v0.y;
            acc[0].z += u.z * v0.z; acc[0].w += u.w * v0.w;
            acc[1].x += u.x * v1.x; acc[1].y += u.y * v1.y;
            acc[1].z += u.z * v1.z; acc[1].w += u.w * v1.w;
            acc[2].x += u.x * v2.x; acc[2].y += u.y * v2.y;
            acc[2].z += u.z * v2.z; acc[2].w += u.w * v2.w;
            acc[3].x += u.x * v3.x; acc[3].y += u.y * v3.y;
            acc[3].z += u.z * v3.z; acc[3].w += u.w * v3.w;
        }

#pragma unroll
        for (int bs = 0; bs < NB; bs++) {
            float a = (acc[bs].x + acc[bs].y) + (acc[bs].z + acc[bs].w);
            pres[bs * LC + lc] = a + br;
            xsm[bs * LC + lc]  = xv[bs];
        }
        __syncthreads();

        if (lc < 64) {
            const int nxt = cur ^ 1;
#pragma unroll
            for (int bs = 0; bs < NB; bs++) {
                float z = sigf(xsm[bs * LC + lc]       + pres[bs * LC + lc]);
                float r = sigf(xsm[bs * LC + 64 + lc]  + pres[bs * LC + 64 + lc]);
                float cand =   xsm[bs * LC + 128 + lc] + r * pres[bs * LC + 128 + lc];
                float hh = sigf(cand);
                float ho = hc[bs * H + rank * 64 + lc];
                float hn = z * ho + (1.0f - z) * hh;

                int b = bgrp * NB + bs;
                g_seq[((size_t)b * TLEN + t) * H + rank * 64 + lc] = hn;

                uint32_t dst = hsb_u32 +
                    (uint32_t)((nxt * (NB * H) + bs * H + rank * 64 + lc) * 4);
#pragma unroll
                for (uint32_t rr = 0; rr < 4; rr++) st_cluster_f32(dst, rr, hn);
            }
        }
        CLUSTER_SYNC_ASM();

#pragma unroll
        for (int bs = 0; bs < NB; bs++) xv[bs] = xn[bs];
    }
}

// ---------------------------------------------------------------------------
// Output head: out[b] = sigmoid(h3[b,:] . Wo + bo)
// ---------------------------------------------------------------------------
__global__ void head_kernel(const float* __restrict__ Wo,
                            const float* __restrict__ bo,
                            float* __restrict__ out)
{
    int b = threadIdx.x;
    if (b < BSZ) {
        float s = bo[0];
#pragma unroll
        for (int k = 0; k < 64; k++) s += g_hA[b * 64 + k] * Wo[k];
        out[b] = sigf(s);
    }
}

// ---------------------------------------------------------------------------
// kernel_launch: 7 launches, graph-capturable, allocation-free, deterministic.
// Inputs: text, W1, U1, b1, W2, U2, b2, W3, U3, b3, Wo, bo
// ---------------------------------------------------------------------------
extern "C" void kernel_launch(void* const* d_in, const int* in_sizes, int n_in,
                              void* d_out, int out_size)
{
    (void)in_sizes; (void)n_in; (void)out_size;

    const float* text = (const float*)d_in[0];
    const float* W1   = (const float*)d_in[1];
    const float* U1   = (const float*)d_in[2];
    const float* b1   = (const float*)d_in[3];
    const float* W2   = (const float*)d_in[4];
    const float* U2   = (const float*)d_in[5];
    const float* b2   = (const float*)d_in[6];
    const float* W3   = (const float*)d_in[7];
    const float* U3   = (const float*)d_in[8];
    const float* b3   = (const float*)d_in[9];
    const float* Wo   = (const float*)d_in[10];
    const float* bo   = (const float*)d_in[11];
    float* out = (float*)d_out;

    const int M = BSZ * TLEN;                 // 65536
    dim3 gblk(16, 16);

    // Dynamic smem sizes (bytes)
    const size_t smem_l1 = (size_t)(192 * 260 + 2 * 4 * 256 + 4 * 192 + 4 * 192) * 4;
    const size_t smem_l2 = (size_t)(384 * 132 + 128 + 384 + 384) * 4;
    const size_t smem_l3 = (size_t)(192 * 68 + 64 + 192 + 192) * 4;

    static int attrs_set = 0;
    if (!attrs_set) {
        cudaFuncSetAttribute(gru_layer1_kernel,
                             cudaFuncAttributeMaxDynamicSharedMemorySize, (int)smem_l1);
        cudaFuncSetAttribute((const void*)gru_layer_smem_kernel<128, false, true>,
                             cudaFuncAttributeMaxDynamicSharedMemorySize, (int)smem_l2);
        cudaFuncSetAttribute((const void*)gru_layer_smem_kernel<64, true, false>,
                             cudaFuncAttributeMaxDynamicSharedMemorySize, (int)smem_l3);
        attrs_set = 1;
    }

    // ---- Layer 1: F=128 -> H=256, sigmoid candidate, return sequences ----
    gemm_bias_kernel<<<dim3(768 / 64, M / 64), gblk>>>(text, W1, b1, 128, 768);
    gru_layer1_kernel<<<dim3(4, 32), 192, smem_l1>>>(U1, b1 + 768);

    // ---- Layer 2: H=256 -> H=128, sigmoid candidate, return sequences ----
    gemm_bias_kernel<<<dim3(384 / 64, M / 64), gblk>>>(nullptr, W2, b2, 256, 384);
    gru_layer_smem_kernel<128, false, true><<<BSZ, 384, smem_l2>>>(U2, b2 + 384);

    // ---- Layer 3: H=128 -> H=64, relu candidate, last state only ----
    gemm_bias_kernel<<<dim3(192 / 64, M / 64), gblk>>>(nullptr, W3, b3, 128, 192);
    gru_layer_smem_kernel<64, true, false><<<BSZ, 192, smem_l3>>>(U3, b3 + 192);

    // ---- Head ----
    head_kernel<<<1, 128>>>(Wo, bo, out);
}

// round 8
// speedup vs baseline: 1.1935x; 1.1935x over previous
#include <cuda_runtime.h>
#include <math.h>
#include <stdint.h>

// Problem constants
#define BSZ  128
#define TLEN 512
// H1=256, H2=128, H3=64

// ---------------------------------------------------------------------------
// Static device scratch (no runtime allocation).
// ---------------------------------------------------------------------------
__device__ float g_xg[(size_t)BSZ * TLEN * 768];
__device__ float g_seq[(size_t)BSZ * TLEN * 256];
__device__ float g_hA[BSZ * 64];

__device__ __forceinline__ float sigf(float x) { return 1.0f / (1.0f + expf(-x)); }

__device__ __forceinline__ uint32_t smem_u32(const void* p) {
    uint32_t a;
    asm("{ .reg .u64 t; cvta.to.shared.u64 t, %1; cvt.u32.u64 %0, t; }"
        : "=r"(a) : "l"(p));
    return a;
}

__device__ __forceinline__ void st_cluster_f32(uint32_t laddr, uint32_t rank, float v) {
    uint32_t r;
    asm volatile("mapa.shared::cluster.u32 %0, %1, %2;" : "=r"(r) : "r"(laddr), "r"(rank));
    asm volatile("st.shared::cluster.b32 [%0], %1;" :: "r"(r), "r"(__float_as_uint(v)) : "memory");
}

#define CLUSTER_SYNC_ASM() do {                                          \
    asm volatile("barrier.cluster.arrive.aligned;" ::: "memory");        \
    asm volatile("barrier.cluster.wait.aligned;"   ::: "memory");        \
} while (0)

// ---------------------------------------------------------------------------
// Tiled SGEMM with bias:  g_xg[m, n] = X[m, :] . W[:, n] + bias[n]
//   X: [M, K] row-major (Xin, or g_seq when Xin == nullptr)
//   W: [K, N] row-major
// 128x64 tile per CTA, BK=16, 256 threads, 8x4 micro-tile.
// Requires M%128==0, N%64==0, K%16==0 (holds for all layers).
// ---------------------------------------------------------------------------
__global__ void __launch_bounds__(256)
gemm_bias_kernel(const float* __restrict__ Xin,
                 const float* __restrict__ W,
                 const float* __restrict__ bias,
                 int K, int N)
{
    const float* __restrict__ X = Xin ? Xin : g_seq;

    __shared__ float As[16][128];   // As[k][m]
    __shared__ float Bs[16][64];    // Bs[k][n]

    const int m0 = blockIdx.y * 128;
    const int n0 = blockIdx.x * 64;
    const int tx = threadIdx.x;     // 0..15 -> n micro-tile (4)
    const int ty = threadIdx.y;     // 0..15 -> m micro-tile (8)
    const int tid = ty * 16 + tx;

    // A load: 128 rows x 16 k, 8 consecutive k per thread (2 float4)
    const int arow = tid >> 1;           // 0..127
    const int acol = (tid & 1) * 8;      // 0 or 8
    // B load: 16 rows x 64 cols, 1 float4 per thread
    const int brow = tid >> 4;           // 0..15
    const int bcol = (tid & 15) * 4;     // 0..60

    float acc[8][4];
#pragma unroll
    for (int i = 0; i < 8; i++)
#pragma unroll
        for (int j = 0; j < 4; j++) acc[i][j] = 0.0f;

    for (int k0 = 0; k0 < K; k0 += 16) {
        float4 av0 = *(const float4*)&X[(size_t)(m0 + arow) * K + k0 + acol];
        float4 av1 = *(const float4*)&X[(size_t)(m0 + arow) * K + k0 + acol + 4];
        As[acol + 0][arow] = av0.x;
        As[acol + 1][arow] = av0.y;
        As[acol + 2][arow] = av0.z;
        As[acol + 3][arow] = av0.w;
        As[acol + 4][arow] = av1.x;
        As[acol + 5][arow] = av1.y;
        As[acol + 6][arow] = av1.z;
        As[acol + 7][arow] = av1.w;

        float4 bv = *(const float4*)&W[(size_t)(k0 + brow) * N + n0 + bcol];
        *(float4*)&Bs[brow][bcol] = bv;

        __syncthreads();

#pragma unroll
        for (int kk = 0; kk < 16; kk++) {
            float4 a0 = *(const float4*)&As[kk][ty * 8];
            float4 a1 = *(const float4*)&As[kk][ty * 8 + 4];
            float4 b  = *(const float4*)&Bs[kk][tx * 4];
            float a[8] = {a0.x, a0.y, a0.z, a0.w, a1.x, a1.y, a1.z, a1.w};
            float bb[4] = {b.x, b.y, b.z, b.w};
#pragma unroll
            for (int i = 0; i < 8; i++)
#pragma unroll
                for (int j = 0; j < 4; j++) acc[i][j] += a[i] * bb[j];
        }
        __syncthreads();
    }

    float bb[4];
#pragma unroll
    for (int j = 0; j < 4; j++) bb[j] = bias[n0 + tx * 4 + j];

#pragma unroll
    for (int i = 0; i < 8; i++) {
        int m = m0 + ty * 8 + i;
        float4 o;
        o.x = acc[i][0] + bb[0];
        o.y = acc[i][1] + bb[1];
        o.z = acc[i][2] + bb[2];
        o.w = acc[i][3] + bb[3];
        *(float4*)&g_xg[(size_t)m * N + n0 + tx * 4] = o;
    }
}

// ---------------------------------------------------------------------------
// Persistent GRU layer with U register-cached (layers 2 and 3).
// One CTA per batch row: grid = 128, block = 3H threads.
// Thread c owns gate-column c. Its U column: first UREG elements in
// registers, remaining (H-UREG) in smem (transposed, padded).
// ---------------------------------------------------------------------------
template <int H, int UREG, bool RELU, bool WSEQ>
__global__ void __launch_bounds__(3 * H, 1)
gru_layer_reg_kernel(const float* __restrict__ U,
                     const float* __restrict__ brec)
{
    constexpr int NC  = 3 * H;
    constexpr int KS  = H - UREG;            // smem-resident tail of k
    constexpr int KSp = (KS > 0) ? KS + 4 : 4;

    extern __shared__ float smem[];
    float* UsT  = smem;                       // [NC][KSp] (if KS>0)
    float* hs   = UsT + (KS > 0 ? NC * KSp : 0);  // [H]
    float* pres = hs + H;                     // [NC]
    float* xsm  = pres + NC;                  // [NC]

    const int b = blockIdx.x;
    const int c = threadIdx.x;                // gate column

    // U register slice (coalesced loads across c).
    float ureg[UREG];
#pragma unroll
    for (int k = 0; k < UREG; k++)
        ureg[k] = U[(size_t)k * NC + c];

    // U smem tail, transposed.
    if constexpr (KS > 0) {
        for (int k = 0; k < KS; k++)
            UsT[c * KSp + k] = U[(size_t)(UREG + k) * NC + c];
    }

    if (c < H) hs[c] = 0.0f;
    const float br = brec[c];
    __syncthreads();

    const float4* h4  = (const float4*)hs;
    const float* xgb  = &g_xg[(size_t)b * TLEN * NC + c];

    float xv = xgb[0];                        // prefetch t=0
    for (int t = 0; t < TLEN; t++) {
        float xn = xgb[(size_t)(t + 1 < TLEN ? t + 1 : t) * NC];

        float4 a4 = make_float4(0.f, 0.f, 0.f, 0.f);
#pragma unroll
        for (int kq = 0; kq < UREG / 4; kq++) {
            float4 hv = h4[kq];               // smem broadcast
            a4.x += ureg[4 * kq + 0] * hv.x;
            a4.y += ureg[4 * kq + 1] * hv.y;
            a4.z += ureg[4 * kq + 2] * hv.z;
            a4.w += ureg[4 * kq + 3] * hv.w;
        }
        if constexpr (KS > 0) {
            const float4* u4  = (const float4*)(UsT + c * KSp);
            const float4* ht4 = (const float4*)(hs + UREG);
#pragma unroll
            for (int kq = 0; kq < KS / 4; kq++) {
                float4 u  = u4[kq];
                float4 hv = ht4[kq];
                a4.x += u.x * hv.x;
                a4.y += u.y * hv.y;
                a4.z += u.z * hv.z;
                a4.w += u.w * hv.w;
            }
        }
        pres[c] = (a4.x + a4.y) + (a4.z + a4.w) + br;
        xsm[c]  = xv;
        __syncthreads();

        if (c < H) {
            float z = sigf(xsm[c] + pres[c]);
            float r = sigf(xsm[H + c] + pres[H + c]);
            float cand = xsm[2 * H + c] + r * pres[2 * H + c];
            float hh = RELU ? fmaxf(cand, 0.0f) : sigf(cand);
            float hn = z * hs[c] + (1.0f - z) * hh;
            hs[c] = hn;
            if (WSEQ)
                g_seq[((size_t)b * TLEN + t) * H + c] = hn;
            else if (t == TLEN - 1)
                g_hA[b * H + c] = hn;
        }
        __syncthreads();
        xv = xn;
    }
}

// ---------------------------------------------------------------------------
// Persistent GRU layer 1 (H=256): U1 = 768 KB split across a 4-CTA cluster.
// Cluster rank r owns h-columns [r*64, (r+1)*64) -> 192 gate-columns in smem.
// Each cluster processes 4 batch rows; grid = (4, 32) -> 32 clusters.
// ---------------------------------------------------------------------------
__global__ void __cluster_dims__(4, 1, 1) __launch_bounds__(192, 1)
gru_layer1_kernel(const float* __restrict__ U,
                  const float* __restrict__ brec)
{
    constexpr int H = 256, NC3 = 768;
    constexpr int LC = 192;            // local gate-columns per CTA
    constexpr int Hp = 260;            // pad: 260 % 32 == 4
    constexpr int NB = 4;              // batches per cluster

    extern __shared__ float smem[];
    float* UsT  = smem;                       // [192][260]
    float* hsb  = UsT + LC * Hp;              // [2][NB][256] double-buffered h
    float* pres = hsb + 2 * NB * H;           // [NB][192]
    float* xsm  = pres + NB * LC;             // [NB][192]

    const int lc = threadIdx.x;               // 0..191
    uint32_t rank;
    asm("mov.u32 %0, %%cluster_ctarank;" : "=r"(rank));
    const int bgrp = blockIdx.y;              // 0..31

    // Load this CTA's U slice, transposed.
    for (int idx = lc; idx < H * LC; idx += LC) {
        int k = idx / LC, cc = idx % LC;
        int gg = cc >> 6, il = cc & 63;
        UsT[cc * Hp + k] = U[(size_t)k * NC3 + gg * H + rank * 64 + il];
    }
    for (int idx = lc; idx < 2 * NB * H; idx += LC) hsb[idx] = 0.0f;

    const int gg = lc >> 6, il = lc & 63;
    const int gc = gg * H + rank * 64 + il;   // global gate column
    const float br = brec[gc];
    const uint32_t hsb_u32 = smem_u32(hsb);

    __syncthreads();
    CLUSTER_SYNC_ASM();                       // all CTAs initialized

    const float4* u4 = (const float4*)(UsT + lc * Hp);

    float xv[NB];
#pragma unroll
    for (int bs = 0; bs < NB; bs++)
        xv[bs] = g_xg[((size_t)(bgrp * NB + bs) * TLEN + 0) * NC3 + gc];

    for (int t = 0; t < TLEN; t++) {
        const int cur = t & 1;
        const float* hc = hsb + cur * (NB * H);
        const int tn = (t + 1 < TLEN) ? t + 1 : t;

        float xn[NB];
#pragma unroll
        for (int bs = 0; bs < NB; bs++)
            xn[bs] = g_xg[((size_t)(bgrp * NB + bs) * TLEN + tn) * NC3 + gc];

        float4 acc[NB];
#pragma unroll
        for (int bs = 0; bs < NB; bs++) acc[bs] = make_float4(0.f, 0.f, 0.f, 0.f);

        const float4* h40 = (const float4*)(hc + 0 * H);
        const float4* h41 = (const float4*)(hc + 1 * H);
        const float4* h42 = (const float4*)(hc + 2 * H);
        const float4* h43 = (const float4*)(hc + 3 * H);

#pragma unroll 4
        for (int kq = 0; kq < H / 4; kq++) {
            float4 u = u4[kq];
            float4 v0 = h40[kq], v1 = h41[kq], v2 = h42[kq], v3 = h43[kq];
            acc[0].x += u.x * v0.x; acc[0].y += u.y * v0.y;
            acc[0].z += u.z * v0.z; acc[0].w += u.w * v0.w;
            acc[1].x += u.x * v1.x; acc[1].y += u.y * v1.y;
            acc[1].z += u.z * v1.z; acc[1].w += u.w * v1.w;
            acc[2].x += u.x * v2.x; acc[2].y += u.y * v2.y;
            acc[2].z += u.z * v2.z; acc[2].w += u.w * v2.w;
            acc[3].x += u.x * v3.x; acc[3].y += u.y * v3.y;
            acc[3].z += u.z * v3.z; acc[3].w += u.w * v3.w;
        }

#pragma unroll
        for (int bs = 0; bs < NB; bs++) {
            float a = (acc[bs].x + acc[bs].y) + (acc[bs].z + acc[bs].w);
            pres[bs * LC + lc] = a + br;
            xsm[bs * LC + lc]  = xv[bs];
        }
        __syncthreads();

        // Gate combine + DSMEM broadcast, distributed over all 192 threads.
        const int nxt = cur ^ 1;
#pragma unroll
        for (int item = lc; item < NB * 64; item += LC) {
            int bs = item >> 6, j = item & 63;
            float z = sigf(xsm[bs * LC + j]       + pres[bs * LC + j]);
            float r = sigf(xsm[bs * LC + 64 + j]  + pres[bs * LC + 64 + j]);
            float cand =   xsm[bs * LC + 128 + j] + r * pres[bs * LC + 128 + j];
            float hh = sigf(cand);
            float ho = hc[bs * H + rank * 64 + j];
            float hn = z * ho + (1.0f - z) * hh;

            int b = bgrp * NB + bs;
            g_seq[((size_t)b * TLEN + t) * H + rank * 64 + j] = hn;

            uint32_t dst = hsb_u32 +
                (uint32_t)((nxt * (NB * H) + bs * H + rank * 64 + j) * 4);
#pragma unroll
            for (uint32_t rr = 0; rr < 4; rr++) st_cluster_f32(dst, rr, hn);
        }
        CLUSTER_SYNC_ASM();

#pragma unroll
        for (int bs = 0; bs < NB; bs++) xv[bs] = xn[bs];
    }
}

// ---------------------------------------------------------------------------
// Output head: out[b] = sigmoid(h3[b,:] . Wo + bo)
// ---------------------------------------------------------------------------
__global__ void head_kernel(const float* __restrict__ Wo,
                            const float* __restrict__ bo,
                            float* __restrict__ out)
{
    int b = threadIdx.x;
    if (b < BSZ) {
        float s = bo[0];
#pragma unroll
        for (int k = 0; k < 64; k++) s += g_hA[b * 64 + k] * Wo[k];
        out[b] = sigf(s);
    }
}

// ---------------------------------------------------------------------------
// kernel_launch: 7 launches, graph-capturable, allocation-free, deterministic.
// Inputs: text, W1, U1, b1, W2, U2, b2, W3, U3, b3, Wo, bo
// ---------------------------------------------------------------------------
extern "C" void kernel_launch(void* const* d_in, const int* in_sizes, int n_in,
                              void* d_out, int out_size)
{
    (void)in_sizes; (void)n_in; (void)out_size;

    const float* text = (const float*)d_in[0];
    const float* W1   = (const float*)d_in[1];
    const float* U1   = (const float*)d_in[2];
    const float* b1   = (const float*)d_in[3];
    const float* W2   = (const float*)d_in[4];
    const float* U2   = (const float*)d_in[5];
    const float* b2   = (const float*)d_in[6];
    const float* W3   = (const float*)d_in[7];
    const float* U3   = (const float*)d_in[8];
    const float* b3   = (const float*)d_in[9];
    const float* Wo   = (const float*)d_in[10];
    const float* bo   = (const float*)d_in[11];
    float* out = (float*)d_out;

    const int M = BSZ * TLEN;                 // 65536
    dim3 gblk(16, 16);

    // Dynamic smem sizes (bytes)
    const size_t smem_l1 = (size_t)(192 * 260 + 2 * 4 * 256 + 4 * 192 + 4 * 192) * 4;
    const size_t smem_l2 = (size_t)(384 * 36 + 128 + 384 + 384) * 4;   // KS=32,KSp=36
    const size_t smem_l3 = (size_t)(64 + 192 + 192) * 4;               // KS=0

    static int attrs_set = 0;
    if (!attrs_set) {
        cudaFuncSetAttribute(gru_layer1_kernel,
                             cudaFuncAttributeMaxDynamicSharedMemorySize, (int)smem_l1);
        cudaFuncSetAttribute((const void*)gru_layer_reg_kernel<128, 96, false, true>,
                             cudaFuncAttributeMaxDynamicSharedMemorySize, (int)smem_l2);
        cudaFuncSetAttribute((const void*)gru_layer_reg_kernel<64, 64, true, false>,
                             cudaFuncAttributeMaxDynamicSharedMemorySize, (int)smem_l3);
        attrs_set = 1;
    }

    // ---- Layer 1: F=128 -> H=256, sigmoid candidate, return sequences ----
    gemm_bias_kernel<<<dim3(768 / 64, M / 128), gblk>>>(text, W1, b1, 128, 768);
    gru_layer1_kernel<<<dim3(4, 32), 192, smem_l1>>>(U1, b1 + 768);

    // ---- Layer 2: H=256 -> H=128, sigmoid candidate, return sequences ----
    gemm_bias_kernel<<<dim3(384 / 64, M / 128), gblk>>>(nullptr, W2, b2, 256, 384);
    gru_layer_reg_kernel<128, 96, false, true><<<BSZ, 384, smem_l2>>>(U2, b2 + 384);

    // ---- Layer 3: H=128 -> H=64, relu candidate, last state only ----
    gemm_bias_kernel<<<dim3(192 / 64, M / 128), gblk>>>(nullptr, W3, b3, 128, 192);
    gru_layer_reg_kernel<64, 64, true, false><<<BSZ, 192, smem_l3>>>(U3, b3 + 192);

    // ---- Head ----
    head_kernel<<<1, 128>>>(Wo, bo, out);
}

// round 10
// speedup vs baseline: 1.2666x; 1.0613x over previous
#include <cuda_runtime.h>
#include <cuda_bf16.h>
#include <math.h>
#include <stdint.h>

// Problem constants
#define BSZ  128
#define TLEN 512
// H1=256, H2=128, H3=64

// ---------------------------------------------------------------------------
// Static device scratch (no runtime allocation).
// g_xg      : input-gate projections of current layer, [B*T, 3H] fp32
// g_xh/g_xl : bf16 hi/lo of current GEMM input X ([B*T, K], K<=256)
// g_wth/wtl : bf16 hi/lo of transposed weights WT [N,K]
//             W1T at 0 (768x128), W2T at 98304 (384x256), W3T at 196608 (192x128)
// g_hA      : final hidden state of layer 3 [B, 64] fp32
// ---------------------------------------------------------------------------
__device__ float         g_xg[(size_t)BSZ * TLEN * 768];
__device__ __nv_bfloat16 g_xh[(size_t)BSZ * TLEN * 256];
__device__ __nv_bfloat16 g_xl[(size_t)BSZ * TLEN * 256];
__device__ __nv_bfloat16 g_wth[221184];
__device__ __nv_bfloat16 g_wtl[221184];
__device__ float         g_hA[BSZ * 64];

__device__ __forceinline__ float sigf(float x) { return 1.0f / (1.0f + expf(-x)); }

__device__ __forceinline__ uint32_t smem_u32(const void* p) {
    uint32_t a;
    asm("{ .reg .u64 t; cvta.to.shared.u64 t, %1; cvt.u32.u64 %0, t; }"
        : "=r"(a) : "l"(p));
    return a;
}

__device__ __forceinline__ void st_cluster_f32(uint32_t laddr, uint32_t rank, float v) {
    uint32_t r;
    asm volatile("mapa.shared::cluster.u32 %0, %1, %2;" : "=r"(r) : "r"(laddr), "r"(rank));
    asm volatile("st.shared::cluster.b32 [%0], %1;" :: "r"(r), "r"(__float_as_uint(v)) : "memory");
}

#define CLUSTER_SYNC_ASM() do {                                          \
    asm volatile("barrier.cluster.arrive.aligned;" ::: "memory");        \
    asm volatile("barrier.cluster.wait.aligned;"   ::: "memory");        \
} while (0)

// bf16 hi/lo split of an fp32 value
__device__ __forceinline__ void bf16_split(float a, __nv_bfloat16& hi, __nv_bfloat16& lo) {
    hi = __float2bfloat16_rn(a);
    lo = __float2bfloat16_rn(a - __bfloat162float(hi));
}

// m16n8k16 bf16 MMA, fp32 accumulate (sm_80 baseline PTX; compiles at compute_103)
#define MMA_BF16(c, a, b)                                                       \
    asm volatile(                                                               \
        "mma.sync.aligned.m16n8k16.row.col.f32.bf16.bf16.f32 "                  \
        "{%0,%1,%2,%3}, {%4,%5,%6,%7}, {%8,%9}, {%0,%1,%2,%3};"                 \
        : "+f"((c)[0]), "+f"((c)[1]), "+f"((c)[2]), "+f"((c)[3])                \
        : "r"((a)[0]), "r"((a)[1]), "r"((a)[2]), "r"((a)[3]),                   \
          "r"((b)[0]), "r"((b)[1]))

// ---------------------------------------------------------------------------
// Weight transpose + bf16 hi/lo split:  W [K,N] fp32 -> WT_hi/WT_lo [N,K] bf16
// ---------------------------------------------------------------------------
__global__ void wsplit_kernel(const float* __restrict__ W, int K, int N, int off)
{
    int idx = blockIdx.x * 256 + threadIdx.x;
    if (idx < K * N) {
        int k = idx / N, n = idx % N;
        __nv_bfloat16 hi, lo;
        bf16_split(W[idx], hi, lo);
        g_wth[off + (size_t)n * K + k] = hi;
        g_wtl[off + (size_t)n * K + k] = lo;
    }
}

// ---------------------------------------------------------------------------
// X split: fp32 [n] -> g_xh/g_xl bf16 (used once, for `text`)
// ---------------------------------------------------------------------------
__global__ void xsplit_kernel(const float* __restrict__ X, int n)
{
    int idx = blockIdx.x * 256 + threadIdx.x;
    if (idx < n) {
        __nv_bfloat16 hi, lo;
        bf16_split(X[idx], hi, lo);
        g_xh[idx] = hi;
        g_xl[idx] = lo;
    }
}

// ---------------------------------------------------------------------------
// bf16x3 tensor-core GEMM with bias: g_xg[m,n] = X[m,:] . W[:,n] + bias[n]
//   X hi/lo: g_xh/g_xl [M,K] row-major bf16
//   WT hi/lo: g_wth/g_wtl + wt_off, [Ntot,K] row-major bf16 (= B col-major)
// CTA tile 128(M) x 64(N), 8 warps in 4x2 (each 32x32), BK=32.
// Smem row stride 40 bf16 -> conflict-free fragment loads.
// D = XhiWhi + XhiWlo + XloWhi accumulated in fp32.
// ---------------------------------------------------------------------------
__global__ void __launch_bounds__(256, 2)
gemm_mma_kernel(const float* __restrict__ bias, int K, int Ntot, int wt_off)
{
    __shared__ __nv_bfloat16 Ah[128 * 40], Al[128 * 40];
    __shared__ __nv_bfloat16 Bh[64 * 40],  Bl[64 * 40];

    const int tid  = threadIdx.x;
    const int wid  = tid >> 5;
    const int lane = tid & 31;
    const int wm   = wid & 3;        // warp m-tile (32 rows)
    const int wn   = wid >> 2;       // warp n-tile (32 cols)
    const int m0   = blockIdx.y * 128;
    const int n0   = blockIdx.x * 64;
    const int g    = lane >> 2;      // groupID
    const int tg   = lane & 3;       // thread in group

    const __nv_bfloat16* wth = g_wth + wt_off;
    const __nv_bfloat16* wtl = g_wtl + wt_off;

    float c[2][4][4];
#pragma unroll
    for (int mt = 0; mt < 2; mt++)
#pragma unroll
        for (int nt = 0; nt < 4; nt++)
#pragma unroll
            for (int i = 0; i < 4; i++) c[mt][nt][i] = 0.0f;

    for (int k0 = 0; k0 < K; k0 += 32) {
        // ---- stage A chunk [128 x 32] hi+lo (512 uint4 each) ----
#pragma unroll
        for (int it = tid; it < 512; it += 256) {
            int r = it >> 2, q = it & 3;            // row, 8-bf16 quad
            size_t go = (size_t)(m0 + r) * K + k0 + q * 8;
            *(uint4*)&Ah[r * 40 + q * 8] = *(const uint4*)&g_xh[go];
            *(uint4*)&Al[r * 40 + q * 8] = *(const uint4*)&g_xl[go];
        }
        // ---- stage B chunk [64 x 32] hi+lo (256 uint4 each) ----
        {
            int r = tid >> 2, q = tid & 3;
            size_t go = (size_t)(n0 + r) * K + k0 + q * 8;
            *(uint4*)&Bh[r * 40 + q * 8] = *(const uint4*)&wth[go];
            *(uint4*)&Bl[r * 40 + q * 8] = *(const uint4*)&wtl[go];
        }
        __syncthreads();

#pragma unroll
        for (int ks = 0; ks < 2; ks++) {             // two k16 steps
            uint32_t ah[2][4], al[2][4], bh[4][2], bl[4][2];
            const int cb = ks * 16 + tg * 2;
#pragma unroll
            for (int mt = 0; mt < 2; mt++) {
                int r0 = wm * 32 + mt * 16 + g;
                ah[mt][0] = *(const uint32_t*)&Ah[(r0    ) * 40 + cb];
                ah[mt][1] = *(const uint32_t*)&Ah[(r0 + 8) * 40 + cb];
                ah[mt][2] = *(const uint32_t*)&Ah[(r0    ) * 40 + cb + 8];
                ah[mt][3] = *(const uint32_t*)&Ah[(r0 + 8) * 40 + cb + 8];
                al[mt][0] = *(const uint32_t*)&Al[(r0    ) * 40 + cb];
                al[mt][1] = *(const uint32_t*)&Al[(r0 + 8) * 40 + cb];
                al[mt][2] = *(const uint32_t*)&Al[(r0    ) * 40 + cb + 8];
                al[mt][3] = *(const uint32_t*)&Al[(r0 + 8) * 40 + cb + 8];
            }
#pragma unroll
            for (int nt = 0; nt < 4; nt++) {
                int rn = wn * 32 + nt * 8 + g;
                bh[nt][0] = *(const uint32_t*)&Bh[rn * 40 + cb];
                bh[nt][1] = *(const uint32_t*)&Bh[rn * 40 + cb + 8];
                bl[nt][0] = *(const uint32_t*)&Bl[rn * 40 + cb];
                bl[nt][1] = *(const uint32_t*)&Bl[rn * 40 + cb + 8];
            }
#pragma unroll
            for (int mt = 0; mt < 2; mt++)
#pragma unroll
                for (int nt = 0; nt < 4; nt++) {
                    MMA_BF16(c[mt][nt], ah[mt], bh[nt]);
                    MMA_BF16(c[mt][nt], ah[mt], bl[nt]);
                    MMA_BF16(c[mt][nt], al[mt], bh[nt]);
                }
        }
        __syncthreads();
    }

    // ---- epilogue: add bias, store fp32 ----
#pragma unroll
    for (int mt = 0; mt < 2; mt++)
#pragma unroll
        for (int nt = 0; nt < 4; nt++) {
            int row = m0 + wm * 32 + mt * 16 + g;
            int col = n0 + wn * 32 + nt * 8 + tg * 2;
            float b0 = bias[col], b1 = bias[col + 1];
            float2 o0 = make_float2(c[mt][nt][0] + b0, c[mt][nt][1] + b1);
            float2 o1 = make_float2(c[mt][nt][2] + b0, c[mt][nt][3] + b1);
            *(float2*)&g_xg[(size_t)row * Ntot + col]       = o0;
            *(float2*)&g_xg[(size_t)(row + 8) * Ntot + col] = o1;
        }
}

// ---------------------------------------------------------------------------
// Persistent GRU layer with U register-cached (layers 2 and 3).
// Sequence output written as bf16 hi/lo (consumed only by the next GEMM).
// ---------------------------------------------------------------------------
template <int H, int UREG, bool RELU, bool WSEQ>
__global__ void __launch_bounds__(3 * H, 1)
gru_layer_reg_kernel(const float* __restrict__ U,
                     const float* __restrict__ brec)
{
    constexpr int NC  = 3 * H;
    constexpr int KS  = H - UREG;
    constexpr int KSp = (KS > 0) ? KS + 4 : 4;

    extern __shared__ float smem[];
    float* UsT  = smem;
    float* hs   = UsT + (KS > 0 ? NC * KSp : 0);
    float* pres = hs + H;
    float* xsm  = pres + NC;

    const int b = blockIdx.x;
    const int c = threadIdx.x;

    float ureg[UREG];
#pragma unroll
    for (int k = 0; k < UREG; k++)
        ureg[k] = U[(size_t)k * NC + c];

    if constexpr (KS > 0) {
        for (int k = 0; k < KS; k++)
            UsT[c * KSp + k] = U[(size_t)(UREG + k) * NC + c];
    }

    if (c < H) hs[c] = 0.0f;
    const float br = brec[c];
    __syncthreads();

    const float4* h4  = (const float4*)hs;
    const float* xgb  = &g_xg[(size_t)b * TLEN * NC + c];

    float xv = xgb[0];
    for (int t = 0; t < TLEN; t++) {
        float xn = xgb[(size_t)(t + 1 < TLEN ? t + 1 : t) * NC];

        float4 a4 = make_float4(0.f, 0.f, 0.f, 0.f);
#pragma unroll
        for (int kq = 0; kq < UREG / 4; kq++) {
            float4 hv = h4[kq];
            a4.x += ureg[4 * kq + 0] * hv.x;
            a4.y += ureg[4 * kq + 1] * hv.y;
            a4.z += ureg[4 * kq + 2] * hv.z;
            a4.w += ureg[4 * kq + 3] * hv.w;
        }
        if constexpr (KS > 0) {
            const float4* u4  = (const float4*)(UsT + c * KSp);
            const float4* ht4 = (const float4*)(hs + UREG);
#pragma unroll
            for (int kq = 0; kq < KS / 4; kq++) {
                float4 u  = u4[kq];
                float4 hv = ht4[kq];
                a4.x += u.x * hv.x;
                a4.y += u.y * hv.y;
                a4.z += u.z * hv.z;
                a4.w += u.w * hv.w;
            }
        }
        pres[c] = (a4.x + a4.y) + (a4.z + a4.w) + br;
        xsm[c]  = xv;
        __syncthreads();

        if (c < H) {
            float z = sigf(xsm[c] + pres[c]);
            float r = sigf(xsm[H + c] + pres[H + c]);
            float cand = xsm[2 * H + c] + r * pres[2 * H + c];
            float hh = RELU ? fmaxf(cand, 0.0f) : sigf(cand);
            float hn = z * hs[c] + (1.0f - z) * hh;
            hs[c] = hn;
            if (WSEQ) {
                size_t sidx = ((size_t)b * TLEN + t) * H + c;
                __nv_bfloat16 hi, lo;
                bf16_split(hn, hi, lo);
                g_xh[sidx] = hi;
                g_xl[sidx] = lo;
            } else if (t == TLEN - 1) {
                g_hA[b * H + c] = hn;
            }
        }
        __syncthreads();
        xv = xn;
    }
}

// ---------------------------------------------------------------------------
// Persistent GRU layer 1 (H=256): U1 = 768 KB split across a 4-CTA cluster.
// Sequence output written as bf16 hi/lo.
// ---------------------------------------------------------------------------
__global__ void __cluster_dims__(4, 1, 1) __launch_bounds__(192, 1)
gru_layer1_kernel(const float* __restrict__ U,
                  const float* __restrict__ brec)
{
    constexpr int H = 256, NC3 = 768;
    constexpr int LC = 192;
    constexpr int Hp = 260;
    constexpr int NB = 4;

    extern __shared__ float smem[];
    float* UsT  = smem;
    float* hsb  = UsT + LC * Hp;
    float* pres = hsb + 2 * NB * H;
    float* xsm  = pres + NB * LC;

    const int lc = threadIdx.x;
    uint32_t rank;
    asm("mov.u32 %0, %%cluster_ctarank;" : "=r"(rank));
    const int bgrp = blockIdx.y;

    for (int idx = lc; idx < H * LC; idx += LC) {
        int k = idx / LC, cc = idx % LC;
        int gg = cc >> 6, il = cc & 63;
        UsT[cc * Hp + k] = U[(size_t)k * NC3 + gg * H + rank * 64 + il];
    }
    for (int idx = lc; idx < 2 * NB * H; idx += LC) hsb[idx] = 0.0f;

    const int gg = lc >> 6, il = lc & 63;
    const int gc = gg * H + rank * 64 + il;
    const float br = brec[gc];
    const uint32_t hsb_u32 = smem_u32(hsb);

    __syncthreads();
    CLUSTER_SYNC_ASM();

    const float4* u4 = (const float4*)(UsT + lc * Hp);

    float xv[NB];
#pragma unroll
    for (int bs = 0; bs < NB; bs++)
        xv[bs] = g_xg[((size_t)(bgrp * NB + bs) * TLEN + 0) * NC3 + gc];

    for (int t = 0; t < TLEN; t++) {
        const int cur = t & 1;
        const float* hc = hsb + cur * (NB * H);
        const int tn = (t + 1 < TLEN) ? t + 1 : t;

        float xn[NB];
#pragma unroll
        for (int bs = 0; bs < NB; bs++)
            xn[bs] = g_xg[((size_t)(bgrp * NB + bs) * TLEN + tn) * NC3 + gc];

        float4 acc[NB];
#pragma unroll
        for (int bs = 0; bs < NB; bs++) acc[bs] = make_float4(0.f, 0.f, 0.f, 0.f);

        const float4* h40 = (const float4*)(hc + 0 * H);
        const float4* h41 = (const float4*)(hc + 1 * H);
        const float4* h42 = (const float4*)(hc + 2 * H);
        const float4* h43 = (const float4*)(hc + 3 * H);

#pragma unroll 4
        for (int kq = 0; kq < H / 4; kq++) {
            float4 u = u4[kq];
            float4 v0 = h40[kq], v1 = h41[kq], v2 = h42[kq], v3 = h43[kq];
            acc[0].x += u.x * v0.x; acc[0].y += u.y * v0.y;
            acc[0].z += u.z * v0.z; acc[0].w += u.w * v0.w;
            acc[1].x += u.x * v1.x; acc[1].y += u.y * v1.y;
            acc[1].z += u.z * v1.z; acc[1].w += u.w * v1.w;
            acc[2].x += u.x * v2.x; acc[2].y += u.y * v2.y;
            acc[2].z += u.z * v2.z; acc[2].w += u.w * v2.w;
            acc[3].x += u.x * v3.x; acc[3].y += u.y * v3.y;
            acc[3].z += u.z * v3.z; acc[3].w += u.w * v3.w;
        }

#pragma unroll
        for (int bs = 0; bs < NB; bs++) {
            float a = (acc[bs].x + acc[bs].y) + (acc[bs].z + acc[bs].w);
            pres[bs * LC + lc] = a + br;
            xsm[bs * LC + lc]  = xv[bs];
        }
        __syncthreads();

        const int nxt = cur ^ 1;
#pragma unroll
        for (int item = lc; item < NB * 64; item += LC) {
            int bs = item >> 6, j = item & 63;
            float z = sigf(xsm[bs * LC + j]       + pres[bs * LC + j]);
            float r = sigf(xsm[bs * LC + 64 + j]  + pres[bs * LC + 64 + j]);
            float cand =   xsm[bs * LC + 128 + j] + r * pres[bs * LC + 128 + j];
            float hh = sigf(cand);
            float ho = hc[bs * H + rank * 64 + j];
            float hn = z * ho + (1.0f - z) * hh;

            int b = bgrp * NB + bs;
            size_t sidx = ((size_t)b * TLEN + t) * H + rank * 64 + j;
            __nv_bfloat16 hi, lo;
            bf16_split(hn, hi, lo);
            g_xh[sidx] = hi;
            g_xl[sidx] = lo;

            uint32_t dst = hsb_u32 +
                (uint32_t)((nxt * (NB * H) + bs * H + rank * 64 + j) * 4);
#pragma unroll
            for (uint32_t rr = 0; rr < 4; rr++) st_cluster_f32(dst, rr, hn);
        }
        CLUSTER_SYNC_ASM();

#pragma unroll
        for (int bs = 0; bs < NB; bs++) xv[bs] = xn[bs];
    }
}

// ---------------------------------------------------------------------------
// Output head: out[b] = sigmoid(h3[b,:] . Wo + bo)
// ---------------------------------------------------------------------------
__global__ void head_kernel(const float* __restrict__ Wo,
                            const float* __restrict__ bo,
                            float* __restrict__ out)
{
    int b = threadIdx.x;
    if (b < BSZ) {
        float s = bo[0];
#pragma unroll
        for (int k = 0; k < 64; k++) s += g_hA[b * 64 + k] * Wo[k];
        out[b] = sigf(s);
    }
}

// ---------------------------------------------------------------------------
// kernel_launch. Inputs: text, W1, U1, b1, W2, U2, b2, W3, U3, b3, Wo, bo
// ---------------------------------------------------------------------------
extern "C" void kernel_launch(void* const* d_in, const int* in_sizes, int n_in,
                              void* d_out, int out_size)
{
    (void)in_sizes; (void)n_in; (void)out_size;

    const float* text = (const float*)d_in[0];
    const float* W1   = (const float*)d_in[1];
    const float* U1   = (const float*)d_in[2];
    const float* b1   = (const float*)d_in[3];
    const float* W2   = (const float*)d_in[4];
    const float* U2   = (const float*)d_in[5];
    const float* b2   = (const float*)d_in[6];
    const float* W3   = (const float*)d_in[7];
    const float* U3   = (const float*)d_in[8];
    const float* b3   = (const float*)d_in[9];
    const float* Wo   = (const float*)d_in[10];
    const float* bo   = (const float*)d_in[11];
    float* out = (float*)d_out;

    const int M = BSZ * TLEN;                 // 65536

    // Dynamic smem sizes (bytes) for the GRU kernels
    const size_t smem_l1 = (size_t)(192 * 260 + 2 * 4 * 256 + 4 * 192 + 4 * 192) * 4;
    const size_t smem_l2 = (size_t)(384 * 36 + 128 + 384 + 384) * 4;
    const size_t smem_l3 = (size_t)(64 + 192 + 192) * 4;

    cudaFuncSetAttribute(gru_layer1_kernel,
                         cudaFuncAttributeMaxDynamicSharedMemorySize, (int)smem_l1);
    cudaFuncSetAttribute((const void*)gru_layer_reg_kernel<128, 96, false, true>,
                         cudaFuncAttributeMaxDynamicSharedMemorySize, (int)smem_l2);
    cudaFuncSetAttribute((const void*)gru_layer_reg_kernel<64, 64, true, false>,
                         cudaFuncAttributeMaxDynamicSharedMemorySize, (int)smem_l3);

    // ---- Weight transpose + bf16 split; text split ----
    wsplit_kernel<<<(128 * 768 + 255) / 256, 256>>>(W1, 128, 768, 0);
    wsplit_kernel<<<(256 * 384 + 255) / 256, 256>>>(W2, 256, 384, 98304);
    wsplit_kernel<<<(128 * 192 + 255) / 256, 256>>>(W3, 128, 192, 196608);
    xsplit_kernel<<<(M * 128 + 255) / 256, 256>>>(text, M * 128);

    // ---- Layer 1: F=128 -> H=256, sigmoid candidate, return sequences ----
    gemm_mma_kernel<<<dim3(768 / 64, M / 128), 256>>>(b1, 128, 768, 0);
    gru_layer1_kernel<<<dim3(4, 32), 192, smem_l1>>>(U1, b1 + 768);

    // ---- Layer 2: H=256 -> H=128, sigmoid candidate, return sequences ----
    gemm_mma_kernel<<<dim3(384 / 64, M / 128), 256>>>(b2, 256, 384, 98304);
    gru_layer_reg_kernel<128, 96, false, true><<<BSZ, 384, smem_l2>>>(U2, b2 + 384);

    // ---- Layer 3: H=128 -> H=64, relu candidate, last state only ----
    gemm_mma_kernel<<<dim3(192 / 64, M / 128), 256>>>(b3, 128, 192, 196608);
    gru_layer_reg_kernel<64, 64, true, false><<<BSZ, 192, smem_l3>>>(U3, b3 + 192);

    // ---- Head ----
    head_kernel<<<1, 128>>>(Wo, bo, out);
}

// round 11
// speedup vs baseline: 1.6808x; 1.3270x over previous
#include <cuda_runtime.h>
#include <cuda_bf16.h>
#include <math.h>
#include <stdint.h>

// Problem constants
#define BSZ  128
#define TLEN 512
// H1=256, H2=128, H3=64

// ---------------------------------------------------------------------------
// Static device scratch (no runtime allocation).
// ---------------------------------------------------------------------------
__device__ float         g_xg[(size_t)BSZ * TLEN * 768];
__device__ __nv_bfloat16 g_xh[(size_t)BSZ * TLEN * 256];
__device__ __nv_bfloat16 g_xl[(size_t)BSZ * TLEN * 256];
__device__ __nv_bfloat16 g_wth[221184];
__device__ __nv_bfloat16 g_wtl[221184];
__device__ float         g_hA[BSZ * 64];

typedef unsigned long long ull;

__device__ __forceinline__ float sigf(float x) {
    return __fdividef(1.0f, 1.0f + __expf(-x));
}

__device__ __forceinline__ uint32_t smem_u32(const void* p) {
    uint32_t a;
    asm("{ .reg .u64 t; cvta.to.shared.u64 t, %1; cvt.u32.u64 %0, t; }"
        : "=r"(a) : "l"(p));
    return a;
}

__device__ __forceinline__ void st_cluster_f32(uint32_t laddr, uint32_t rank, float v) {
    uint32_t r;
    asm volatile("mapa.shared::cluster.u32 %0, %1, %2;" : "=r"(r) : "r"(laddr), "r"(rank));
    asm volatile("st.shared::cluster.b32 [%0], %1;" :: "r"(r), "r"(__float_as_uint(v)) : "memory");
}

#define CLUSTER_SYNC_ASM() do {                                          \
    asm volatile("barrier.cluster.arrive.aligned;" ::: "memory");        \
    asm volatile("barrier.cluster.wait.aligned;"   ::: "memory");        \
} while (0)

// Packed dual-fp32 FMA (Blackwell f32x2 pipe): acc += a * b elementwise.
#define FMA_X2(acc, a, b) \
    asm("fma.rn.f32x2 %0, %1, %2, %0;" : "+l"(acc) : "l"(a), "l"(b))

__device__ __forceinline__ ull packf2(float lo, float hi) {
    return (ull)__float_as_uint(lo) | ((ull)__float_as_uint(hi) << 32);
}
__device__ __forceinline__ float sumf2(ull v) {
    return __uint_as_float((uint32_t)v) + __uint_as_float((uint32_t)(v >> 32));
}

// bf16 hi/lo split of an fp32 value
__device__ __forceinline__ void bf16_split(float a, __nv_bfloat16& hi, __nv_bfloat16& lo) {
    hi = __float2bfloat16_rn(a);
    lo = __float2bfloat16_rn(a - __bfloat162float(hi));
}

// m16n8k16 bf16 MMA, fp32 accumulate
#define MMA_BF16(c, a, b)                                                       \
    asm volatile(                                                               \
        "mma.sync.aligned.m16n8k16.row.col.f32.bf16.bf16.f32 "                  \
        "{%0,%1,%2,%3}, {%4,%5,%6,%7}, {%8,%9}, {%0,%1,%2,%3};"                 \
        : "+f"((c)[0]), "+f"((c)[1]), "+f"((c)[2]), "+f"((c)[3])                \
        : "r"((a)[0]), "r"((a)[1]), "r"((a)[2]), "r"((a)[3]),                   \
          "r"((b)[0]), "r"((b)[1]))

// ---------------------------------------------------------------------------
// Weight transpose + bf16 hi/lo split:  W [K,N] fp32 -> WT_hi/WT_lo [N,K] bf16
// ---------------------------------------------------------------------------
__global__ void wsplit_kernel(const float* __restrict__ W, int K, int N, int off)
{
    int idx = blockIdx.x * 256 + threadIdx.x;
    if (idx < K * N) {
        int k = idx / N, n = idx % N;
        __nv_bfloat16 hi, lo;
        bf16_split(W[idx], hi, lo);
        g_wth[off + (size_t)n * K + k] = hi;
        g_wtl[off + (size_t)n * K + k] = lo;
    }
}

// ---------------------------------------------------------------------------
// X split: fp32 [n] -> g_xh/g_xl bf16 (used once, for `text`)
// ---------------------------------------------------------------------------
__global__ void xsplit_kernel(const float* __restrict__ X, int n)
{
    int idx = blockIdx.x * 256 + threadIdx.x;
    if (idx < n) {
        __nv_bfloat16 hi, lo;
        bf16_split(X[idx], hi, lo);
        g_xh[idx] = hi;
        g_xl[idx] = lo;
    }
}

// ---------------------------------------------------------------------------
// bf16x3 tensor-core GEMM with bias (unchanged from R10).
// ---------------------------------------------------------------------------
__global__ void __launch_bounds__(256, 2)
gemm_mma_kernel(const float* __restrict__ bias, int K, int Ntot, int wt_off)
{
    __shared__ __nv_bfloat16 Ah[128 * 40], Al[128 * 40];
    __shared__ __nv_bfloat16 Bh[64 * 40],  Bl[64 * 40];

    const int tid  = threadIdx.x;
    const int wid  = tid >> 5;
    const int lane = tid & 31;
    const int wm   = wid & 3;
    const int wn   = wid >> 2;
    const int m0   = blockIdx.y * 128;
    const int n0   = blockIdx.x * 64;
    const int g    = lane >> 2;
    const int tg   = lane & 3;

    const __nv_bfloat16* wth = g_wth + wt_off;
    const __nv_bfloat16* wtl = g_wtl + wt_off;

    float c[2][4][4];
#pragma unroll
    for (int mt = 0; mt < 2; mt++)
#pragma unroll
        for (int nt = 0; nt < 4; nt++)
#pragma unroll
            for (int i = 0; i < 4; i++) c[mt][nt][i] = 0.0f;

    for (int k0 = 0; k0 < K; k0 += 32) {
#pragma unroll
        for (int it = tid; it < 512; it += 256) {
            int r = it >> 2, q = it & 3;
            size_t go = (size_t)(m0 + r) * K + k0 + q * 8;
            *(uint4*)&Ah[r * 40 + q * 8] = *(const uint4*)&g_xh[go];
            *(uint4*)&Al[r * 40 + q * 8] = *(const uint4*)&g_xl[go];
        }
        {
            int r = tid >> 2, q = tid & 3;
            size_t go = (size_t)(n0 + r) * K + k0 + q * 8;
            *(uint4*)&Bh[r * 40 + q * 8] = *(const uint4*)&wth[go];
            *(uint4*)&Bl[r * 40 + q * 8] = *(const uint4*)&wtl[go];
        }
        __syncthreads();

#pragma unroll
        for (int ks = 0; ks < 2; ks++) {
            uint32_t ah[2][4], al[2][4], bh[4][2], bl[4][2];
            const int cb = ks * 16 + tg * 2;
#pragma unroll
            for (int mt = 0; mt < 2; mt++) {
                int r0 = wm * 32 + mt * 16 + g;
                ah[mt][0] = *(const uint32_t*)&Ah[(r0    ) * 40 + cb];
                ah[mt][1] = *(const uint32_t*)&Ah[(r0 + 8) * 40 + cb];
                ah[mt][2] = *(const uint32_t*)&Ah[(r0    ) * 40 + cb + 8];
                ah[mt][3] = *(const uint32_t*)&Ah[(r0 + 8) * 40 + cb + 8];
                al[mt][0] = *(const uint32_t*)&Al[(r0    ) * 40 + cb];
                al[mt][1] = *(const uint32_t*)&Al[(r0 + 8) * 40 + cb];
                al[mt][2] = *(const uint32_t*)&Al[(r0    ) * 40 + cb + 8];
                al[mt][3] = *(const uint32_t*)&Al[(r0 + 8) * 40 + cb + 8];
            }
#pragma unroll
            for (int nt = 0; nt < 4; nt++) {
                int rn = wn * 32 + nt * 8 + g;
                bh[nt][0] = *(const uint32_t*)&Bh[rn * 40 + cb];
                bh[nt][1] = *(const uint32_t*)&Bh[rn * 40 + cb + 8];
                bl[nt][0] = *(const uint32_t*)&Bl[rn * 40 + cb];
                bl[nt][1] = *(const uint32_t*)&Bl[rn * 40 + cb + 8];
            }
#pragma unroll
            for (int mt = 0; mt < 2; mt++)
#pragma unroll
                for (int nt = 0; nt < 4; nt++) {
                    MMA_BF16(c[mt][nt], ah[mt], bh[nt]);
                    MMA_BF16(c[mt][nt], ah[mt], bl[nt]);
                    MMA_BF16(c[mt][nt], al[mt], bh[nt]);
                }
        }
        __syncthreads();
    }

#pragma unroll
    for (int mt = 0; mt < 2; mt++)
#pragma unroll
        for (int nt = 0; nt < 4; nt++) {
            int row = m0 + wm * 32 + mt * 16 + g;
            int col = n0 + wn * 32 + nt * 8 + tg * 2;
            float b0 = bias[col], b1 = bias[col + 1];
            float2 o0 = make_float2(c[mt][nt][0] + b0, c[mt][nt][1] + b1);
            float2 o1 = make_float2(c[mt][nt][2] + b0, c[mt][nt][3] + b1);
            *(float2*)&g_xg[(size_t)row * Ntot + col]       = o0;
            *(float2*)&g_xg[(size_t)(row + 8) * Ntot + col] = o1;
        }
}

// ---------------------------------------------------------------------------
// Persistent GRU layers 2/3: U register-cached + packed f32x2 FMA.
// One CTA per batch row: grid = 128, block = 3H.
// ---------------------------------------------------------------------------
template <int H, int UREG, bool RELU, bool WSEQ>
__global__ void __launch_bounds__(3 * H, 1)
gru_layer_reg_kernel(const float* __restrict__ U,
                     const float* __restrict__ brec)
{
    constexpr int NC  = 3 * H;
    constexpr int KS  = H - UREG;
    constexpr int KSp = (KS > 0) ? KS + 4 : 4;

    extern __shared__ float smem[];
    float* UsT  = smem;
    float* hs   = UsT + (KS > 0 ? NC * KSp : 0);
    float* pres = hs + H;
    float* xsm  = pres + NC;

    const int b = blockIdx.x;
    const int c = threadIdx.x;

    // U register slice, packed into f32x2 pairs.
    ull upk[UREG / 2];
#pragma unroll
    for (int jp = 0; jp < UREG / 2; jp++) {
        float f0 = U[(size_t)(2 * jp)     * NC + c];
        float f1 = U[(size_t)(2 * jp + 1) * NC + c];
        upk[jp] = packf2(f0, f1);
    }
    if constexpr (KS > 0) {
        for (int k = 0; k < KS; k++)
            UsT[c * KSp + k] = U[(size_t)(UREG + k) * NC + c];
    }

    if (c < H) hs[c] = 0.0f;
    const float br = brec[c];
    __syncthreads();

    const float* xgb = &g_xg[(size_t)b * TLEN * NC + c];

    float xv = xgb[0];
    for (int t = 0; t < TLEN; t++) {
        float xn = xgb[(size_t)(t + 1 < TLEN ? t + 1 : t) * NC];

        ull accA = 0ull, accB = 0ull;
#pragma unroll
        for (int kq = 0; kq < UREG / 4; kq++) {
            ulonglong2 hv = *(const ulonglong2*)&hs[kq * 4];
            FMA_X2(accA, upk[2 * kq],     hv.x);
            FMA_X2(accB, upk[2 * kq + 1], hv.y);
        }
        if constexpr (KS > 0) {
#pragma unroll
            for (int jq = 0; jq < KS / 4; jq++) {
                ulonglong2 uv = *(const ulonglong2*)&UsT[c * KSp + jq * 4];
                ulonglong2 hv = *(const ulonglong2*)&hs[UREG + jq * 4];
                FMA_X2(accA, uv.x, hv.x);
                FMA_X2(accB, uv.y, hv.y);
            }
        }
        pres[c] = sumf2(accA) + sumf2(accB) + br;
        xsm[c]  = xv;
        __syncthreads();

        if (c < H) {
            float z = sigf(xsm[c] + pres[c]);
            float r = sigf(xsm[H + c] + pres[H + c]);
            float cand = xsm[2 * H + c] + r * pres[2 * H + c];
            float hh = RELU ? fmaxf(cand, 0.0f) : sigf(cand);
            float hn = z * hs[c] + (1.0f - z) * hh;
            hs[c] = hn;
            if (WSEQ) {
                size_t sidx = ((size_t)b * TLEN + t) * H + c;
                __nv_bfloat16 hi, lo;
                bf16_split(hn, hi, lo);
                g_xh[sidx] = hi;
                g_xl[sidx] = lo;
            } else if (t == TLEN - 1) {
                g_hA[b * H + c] = hn;
            }
        }
        __syncthreads();
        xv = xn;
    }
}

// ---------------------------------------------------------------------------
// Persistent GRU layer 1 (H=256), 4-CTA cluster, 384 threads/CTA.
// Thread t: gate-col c = t%192 (within CTA's 192-col slice), k-half = t/192.
// U slice per thread (128 k): 96 in registers (packed f32x2) + 32 in smem.
// Per step: packed dots -> partial[half] -> combine+gates -> DSMEM broadcast.
// ---------------------------------------------------------------------------
__global__ void __cluster_dims__(4, 1, 1) __launch_bounds__(384, 1)
gru_layer1_kernel(const float* __restrict__ U,
                  const float* __restrict__ brec)
{
    constexpr int H = 256, NC3 = 768;
    constexpr int NB = 4;              // batches per cluster
    constexpr int UR = 96;             // k in registers per thread
    constexpr int KT = 32;             // k tail in smem per thread

    extern __shared__ float smem[];
    float* hsb  = smem;                 // [2][NB][256] double-buffered h (2048)
    float* Ut   = hsb + 2048;           // [8][384][4] U tail (12288)
    float* part = Ut + 12288;           // [2][192][4] partial sums (1536)
    float* xsm  = part + 1536;          // [192][4] xg staging (768)

    const int t    = threadIdx.x;
    const int half = (t >= 192) ? 1 : 0;      // warps 0-5 / 6-11
    const int c    = t - half * 192;
    uint32_t rank;
    asm("mov.u32 %0, %%cluster_ctarank;" : "=r"(rank));
    const int bgrp = blockIdx.y;

    const int gg = c >> 6, il = c & 63;
    const int gc = gg * H + (int)rank * 64 + il;   // global gate column
    const int kbase = half * 128;

    // U registers (packed pairs) + smem tail
    ull upk[UR / 2];
#pragma unroll
    for (int jp = 0; jp < UR / 2; jp++) {
        float f0 = U[(size_t)(kbase + 2 * jp)     * NC3 + gc];
        float f1 = U[(size_t)(kbase + 2 * jp + 1) * NC3 + gc];
        upk[jp] = packf2(f0, f1);
    }
    for (int j = 0; j < KT; j++)
        Ut[((j >> 2) * 384 + t) * 4 + (j & 3)] = U[(size_t)(kbase + UR + j) * NC3 + gc];

    for (int idx = t; idx < 2 * NB * H; idx += 384) hsb[idx] = 0.0f;

    const float br = brec[gc];
    const uint32_t hsb_u32 = smem_u32(hsb);

    __syncthreads();
    CLUSTER_SYNC_ASM();

    // prefetch xg for t=0 (half-0 threads own xg staging)
    float xv[NB];
    if (half == 0) {
#pragma unroll
        for (int bs = 0; bs < NB; bs++)
            xv[bs] = g_xg[((size_t)(bgrp * NB + bs) * TLEN + 0) * NC3 + gc];
    }

    for (int step = 0; step < TLEN; step++) {
        const int cur = step & 1;
        const int nxt = cur ^ 1;
        const float* hc = hsb + cur * (NB * H);
        const int tn = (step + 1 < TLEN) ? step + 1 : step;

        float xn[NB];
        if (half == 0) {
#pragma unroll
            for (int bs = 0; bs < NB; bs++)
                xn[bs] = g_xg[((size_t)(bgrp * NB + bs) * TLEN + tn) * NC3 + gc];
        }

        ull accA[NB], accB[NB];
#pragma unroll
        for (int bs = 0; bs < NB; bs++) { accA[bs] = 0ull; accB[bs] = 0ull; }

        // main: 96 k from registers, h broadcast from smem
#pragma unroll
        for (int kq = 0; kq < UR / 4; kq++) {
#pragma unroll
            for (int bs = 0; bs < NB; bs++) {
                ulonglong2 hv = *(const ulonglong2*)&hc[bs * H + kbase + kq * 4];
                FMA_X2(accA[bs], upk[2 * kq],     hv.x);
                FMA_X2(accB[bs], upk[2 * kq + 1], hv.y);
            }
        }
        // tail: 32 k from smem (conflict-free [jq][t][4] layout)
#pragma unroll
        for (int jq = 0; jq < KT / 4; jq++) {
            ulonglong2 uv = *(const ulonglong2*)&Ut[(jq * 384 + t) * 4];
#pragma unroll
            for (int bs = 0; bs < NB; bs++) {
                ulonglong2 hv = *(const ulonglong2*)&hc[bs * H + kbase + UR + jq * 4];
                FMA_X2(accA[bs], uv.x, hv.x);
                FMA_X2(accB[bs], uv.y, hv.y);
            }
        }

        float4 ps;
        ps.x = sumf2(accA[0]) + sumf2(accB[0]);
        ps.y = sumf2(accA[1]) + sumf2(accB[1]);
        ps.z = sumf2(accA[2]) + sumf2(accB[2]);
        ps.w = sumf2(accA[3]) + sumf2(accB[3]);
        if (half == 0) {
            ps.x += br; ps.y += br; ps.z += br; ps.w += br;
            *(float4*)&xsm[c * 4] = make_float4(xv[0], xv[1], xv[2], xv[3]);
        }
        *(float4*)&part[(half * 192 + c) * 4] = ps;
        __syncthreads();

        // gate combine + DSMEM broadcast: items (bs, j) over threads < 256
        if (t < 256) {
            const int bs = t >> 6, j = t & 63;
            const int jz = j, jr = 64 + j, jh = 128 + j;
            float pz = part[jz * 4 + bs] + part[(192 + jz) * 4 + bs];
            float pr = part[jr * 4 + bs] + part[(192 + jr) * 4 + bs];
            float ph = part[jh * 4 + bs] + part[(192 + jh) * 4 + bs];
            float z = sigf(xsm[jz * 4 + bs] + pz);
            float r = sigf(xsm[jr * 4 + bs] + pr);
            float cand = xsm[jh * 4 + bs] + r * ph;
            float hh = sigf(cand);
            float hold = hc[bs * H + (int)rank * 64 + j];
            float hn = z * hold + (1.0f - z) * hh;

            int b = bgrp * NB + bs;
            size_t sidx = ((size_t)b * TLEN + step) * H + rank * 64 + j;
            __nv_bfloat16 hi, lo;
            bf16_split(hn, hi, lo);
            g_xh[sidx] = hi;
            g_xl[sidx] = lo;

            uint32_t dst = hsb_u32 +
                (uint32_t)((nxt * (NB * H) + bs * H + (int)rank * 64 + j) * 4);
#pragma unroll
            for (uint32_t rr = 0; rr < 4; rr++) st_cluster_f32(dst, rr, hn);
        }
        CLUSTER_SYNC_ASM();

        if (half == 0) {
#pragma unroll
            for (int bs = 0; bs < NB; bs++) xv[bs] = xn[bs];
        }
    }
}

// ---------------------------------------------------------------------------
// Output head: out[b] = sigmoid(h3[b,:] . Wo + bo)
// ---------------------------------------------------------------------------
__global__ void head_kernel(const float* __restrict__ Wo,
                            const float* __restrict__ bo,
                            float* __restrict__ out)
{
    int b = threadIdx.x;
    if (b < BSZ) {
        float s = bo[0];
#pragma unroll
        for (int k = 0; k < 64; k++) s += g_hA[b * 64 + k] * Wo[k];
        out[b] = sigf(s);
    }
}

// ---------------------------------------------------------------------------
// kernel_launch. Inputs: text, W1, U1, b1, W2, U2, b2, W3, U3, b3, Wo, bo
// ---------------------------------------------------------------------------
extern "C" void kernel_launch(void* const* d_in, const int* in_sizes, int n_in,
                              void* d_out, int out_size)
{
    (void)in_sizes; (void)n_in; (void)out_size;

    const float* text = (const float*)d_in[0];
    const float* W1   = (const float*)d_in[1];
    const float* U1   = (const float*)d_in[2];
    const float* b1   = (const float*)d_in[3];
    const float* W2   = (const float*)d_in[4];
    const float* U2   = (const float*)d_in[5];
    const float* b2   = (const float*)d_in[6];
    const float* W3   = (const float*)d_in[7];
    const float* U3   = (const float*)d_in[8];
    const float* b3   = (const float*)d_in[9];
    const float* Wo   = (const float*)d_in[10];
    const float* bo   = (const float*)d_in[11];
    float* out = (float*)d_out;

    const int M = BSZ * TLEN;                 // 65536

    // Dynamic smem (bytes)
    const size_t smem_l1 = (size_t)(2048 + 12288 + 1536 + 768) * 4;   // 66560
    const size_t smem_l2 = (size_t)(384 * 36 + 128 + 384 + 384) * 4;
    const size_t smem_l3 = (size_t)(64 + 192 + 192) * 4;

    cudaFuncSetAttribute(gru_layer1_kernel,
                         cudaFuncAttributeMaxDynamicSharedMemorySize, (int)smem_l1);
    cudaFuncSetAttribute((const void*)gru_layer_reg_kernel<128, 96, false, true>,
                         cudaFuncAttributeMaxDynamicSharedMemorySize, (int)smem_l2);
    cudaFuncSetAttribute((const void*)gru_layer_reg_kernel<64, 64, true, false>,
                         cudaFuncAttributeMaxDynamicSharedMemorySize, (int)smem_l3);

    // ---- Weight transpose + bf16 split; text split ----
    wsplit_kernel<<<(128 * 768 + 255) / 256, 256>>>(W1, 128, 768, 0);
    wsplit_kernel<<<(256 * 384 + 255) / 256, 256>>>(W2, 256, 384, 98304);
    wsplit_kernel<<<(128 * 192 + 255) / 256, 256>>>(W3, 128, 192, 196608);
    xsplit_kernel<<<(M * 128 + 255) / 256, 256>>>(text, M * 128);

    // ---- Layer 1: F=128 -> H=256, sigmoid candidate, return sequences ----
    gemm_mma_kernel<<<dim3(768 / 64, M / 128), 256>>>(b1, 128, 768, 0);
    gru_layer1_kernel<<<dim3(4, 32), 384, smem_l1>>>(U1, b1 + 768);

    // ---- Layer 2: H=256 -> H=128, sigmoid candidate, return sequences ----
    gemm_mma_kernel<<<dim3(384 / 64, M / 128), 256>>>(b2, 256, 384, 98304);
    gru_layer_reg_kernel<128, 96, false, true><<<BSZ, 384, smem_l2>>>(U2, b2 + 384);

    // ---- Layer 3: H=128 -> H=64, relu candidate, last state only ----
    gemm_mma_kernel<<<dim3(192 / 64, M / 128), 256>>>(b3, 128, 192, 196608);
    gru_layer_reg_kernel<64, 64, true, false><<<BSZ, 192, smem_l3>>>(U3, b3 + 192);

    // ---- Head ----
    head_kernel<<<1, 128>>>(Wo, bo, out);
}